// round 9
// baseline (speedup 1.0000x reference)
#include <cuda_runtime.h>
#include <cuda_bf16.h>
#include <mma.h>
#include <cstdint>

using namespace nvcuda;

#define NN 256
#define MATS (256LL * 256 * 256)

// scratch (static __device__ arrays: allocation-free)
__device__ __nv_bfloat16 g_Phi[MATS], g_Plo[MATS];
__device__ __nv_bfloat16 g_P2hi[MATS], g_P2lo[MATS];
__device__ __nv_bfloat16 g_P3hi[MATS], g_P3lo[MATS];
__device__ float g_d5p[2 * 65536], g_d6p[2 * 65536], g_d7p[2 * 65536];

__device__ __forceinline__ uint32_t smem_u32(const void* p) {
    uint32_t a;
    asm("{ .reg .u64 t; cvta.to.shared.u64 t, %1; cvt.u32.u64 %0, t; }" : "=r"(a) : "l"(p));
    return a;
}
__device__ __forceinline__ void cpa16(uint32_t dst, const void* src) {
    asm volatile("cp.async.cg.shared.global [%0], [%1], 16;" :: "r"(dst), "l"(src));
}
__device__ __forceinline__ void cpa_commit() {
    asm volatile("cp.async.commit_group;" ::: "memory");
}
__device__ __forceinline__ float bf2f(__nv_bfloat16 v) { return __bfloat162float(v); }

// ---------------------------------------------------------------------------
// prep: threshold + row-normalize. Warp per row. Writes bf16 hi/lo of P +
// slots 0/1.
// ---------------------------------------------------------------------------
__global__ void __launch_bounds__(256) prep_kernel(const float* __restrict__ A,
                                                   __nv_bfloat16* __restrict__ Phi,
                                                   __nv_bfloat16* __restrict__ Plo,
                                                   float* __restrict__ out)
{
    int row = blockIdx.x * 8 + (threadIdx.x >> 5);
    int lane = threadIdx.x & 31;
    int n = row & 255;

    const float* arow = A + (size_t)row * NN + lane * 8;
    float4 v0 = *(const float4*)(arow);
    float4 v1 = *(const float4*)(arow + 4);
    float f[8] = {v0.x, v0.y, v0.z, v0.w, v1.x, v1.y, v1.z, v1.w};
    float s = 0.0f;
    #pragma unroll
    for (int q = 0; q < 8; q++) {
        f[q] = (f[q] > 0.3f) ? f[q] : 0.0f;
        s += f[q];
    }
    #pragma unroll
    for (int o = 16; o; o >>= 1) s += __shfl_xor_sync(0xffffffffu, s, o);
    float dinv = (s > 0.0f) ? (1.0f / s) : 0.0f;

    uint32_t hp[4], lp[4];
    float p[8];
    #pragma unroll
    for (int q = 0; q < 4; q++) {
        p[2*q]   = f[2*q]   * dinv;
        p[2*q+1] = f[2*q+1] * dinv;
        __nv_bfloat16 h0 = __float2bfloat16_rn(p[2*q]);
        __nv_bfloat16 h1 = __float2bfloat16_rn(p[2*q+1]);
        __nv_bfloat162 hh; hh.x = h0; hh.y = h1;
        hp[q] = *(uint32_t*)&hh;
        __nv_bfloat162 ll;
        ll.x = __float2bfloat16_rn(p[2*q]   - bf2f(h0));
        ll.y = __float2bfloat16_rn(p[2*q+1] - bf2f(h1));
        lp[q] = *(uint32_t*)&ll;
    }
    size_t idx = (size_t)row * NN + lane * 8;
    *(uint4*)(Phi + idx) = make_uint4(hp[0], hp[1], hp[2], hp[3]);
    *(uint4*)(Plo + idx) = make_uint4(lp[0], lp[1], lp[2], lp[3]);

    if (lane == (n >> 3)) out[(size_t)row * 8 + 1] = p[n & 7];
    if (lane == 0)        out[(size_t)row * 8 + 0] = 1.0f;
}

// ---------------------------------------------------------------------------
// WMMA bf16-split GEMM, 3-stage cp.async pipeline (R8 mainloop).
// mode 0: write Chi/Clo + diag slot                         (P2 = P*P)
// mode 1: mode0 + d5 partials via Slab(P2) x staged-C cols  (P3 = P*P2)
// mode 2: NO C write; diag slot + d6,d7 partials via two
//         P3 slabs x staged-C cols                          (P4 = P2*P2)
// ---------------------------------------------------------------------------
#define XLD 40
#define YLD 136
#define XARR_B (128 * XLD * 2)               // 10240
#define YARR_B (32 * YLD * 2)                // 8704
#define OFF_XL XARR_B
#define OFF_YH (2 * XARR_B)
#define OFF_YL (2 * XARR_B + YARR_B)
#define STAGE_B (2 * XARR_B + 2 * YARR_B)    // 37888
#define GEMM_SMEM (3 * STAGE_B)              // 113664 (2 CTA/SM)
#define CLD 132                              // C stage ld: 128*132*4 = 67584
#define CS_B (128 * CLD * 4)
#define SLDA 132                             // slabA: 32 x 132 fp32 = 16896
#define SPA_OFF CS_B
#define SLDB 36                              // slabB: 128 x 36 fp32 = 18432
#define SPB_OFF (CS_B + 32 * SLDA * 4)       // 84480; end 102912 <= 113664

__global__ void __launch_bounds__(256, 2)
gemm_wmma(int mode,
          const __nv_bfloat16* __restrict__ Xh, const __nv_bfloat16* __restrict__ Xl,
          const __nv_bfloat16* __restrict__ Yh, const __nv_bfloat16* __restrict__ Yl,
          __nv_bfloat16* __restrict__ Chi, __nv_bfloat16* __restrict__ Clo, int slot,
          const __nv_bfloat16* __restrict__ SlabH, const __nv_bfloat16* __restrict__ SlabL,
          float* __restrict__ pA, float* __restrict__ pB,
          float* __restrict__ out)
{
    int b = blockIdx.y;
    size_t base = (size_t)b << 16;
    Xh += base; Xl += base; Yh += base; Yl += base;
    int tileM = (blockIdx.x >> 1) << 7;
    int tileN = (blockIdx.x & 1) << 7;

    extern __shared__ __align__(128) char sm[];
    uint32_t smb = smem_u32(sm);

    int t = threadIdx.x;
    int w = t >> 5, wm = w & 1, wn = w >> 1;

    int xr = t >> 1, xq = t & 1;   // X: 128 rows x 2x32B
    int yr = t >> 4, yq = t & 15;  // Y: 32 rows x 16x16B

    wmma::fragment<wmma::accumulator, 16, 16, 16, float> acc[4][2];
    #pragma unroll
    for (int i = 0; i < 4; i++)
        #pragma unroll
        for (int j = 0; j < 2; j++) wmma::fill_fragment(acc[i][j], 0.0f);

    auto issue = [&](int kc, int s) {
        int k0 = kc << 5;
        uint32_t sb = smb + s * STAGE_B;
        {
            const __nv_bfloat16* gh = Xh + (size_t)(tileM + xr) * NN + k0 + xq * 16;
            const __nv_bfloat16* gl = Xl + (size_t)(tileM + xr) * NN + k0 + xq * 16;
            uint32_t d = sb + xr * (XLD * 2) + xq * 32;
            cpa16(d, gh);               cpa16(d + 16, gh + 8);
            cpa16(d + OFF_XL, gl);      cpa16(d + OFF_XL + 16, gl + 8);
        }
        {
            const __nv_bfloat16* gh = Yh + (size_t)(k0 + yr) * NN + tileN + yq * 8;
            const __nv_bfloat16* gl = Yl + (size_t)(k0 + yr) * NN + tileN + yq * 8;
            uint32_t d = sb + OFF_YH + yr * (YLD * 2) + yq * 16;
            cpa16(d, gh);               cpa16(d + 16 * (YLD * 2), gh + 16 * NN);
            cpa16(d + YARR_B, gl);      cpa16(d + YARR_B + 16 * (YLD * 2), gl + 16 * NN);
        }
        cpa_commit();
    };

    issue(0, 0);
    issue(1, 1);

    int scur = 0, sis = 2;
    #pragma unroll 1
    for (int kc = 0; kc < 8; kc++) {
        if (kc < 6) asm volatile("cp.async.wait_group 1;" ::: "memory");
        else        asm volatile("cp.async.wait_group 0;" ::: "memory");
        __syncthreads();
        if (kc < 6) issue(kc + 2, sis);

        const char* sb = sm + scur * STAGE_B;
        const __nv_bfloat16* bXh = (const __nv_bfloat16*)(sb);
        const __nv_bfloat16* bXl = (const __nv_bfloat16*)(sb + OFF_XL);
        const __nv_bfloat16* bYh = (const __nv_bfloat16*)(sb + OFF_YH);
        const __nv_bfloat16* bYl = (const __nv_bfloat16*)(sb + OFF_YL);

        #pragma unroll
        for (int kk = 0; kk < 2; kk++) {
            int ks = kk * 16;
            wmma::fragment<wmma::matrix_a, 16, 16, 16, __nv_bfloat16, wmma::row_major> ah[4], al[4];
            wmma::fragment<wmma::matrix_b, 16, 16, 16, __nv_bfloat16, wmma::row_major> bh[2], bl[2];
            #pragma unroll
            for (int i = 0; i < 4; i++) {
                wmma::load_matrix_sync(ah[i], bXh + (wm * 64 + i * 16) * XLD + ks, XLD);
                wmma::load_matrix_sync(al[i], bXl + (wm * 64 + i * 16) * XLD + ks, XLD);
            }
            #pragma unroll
            for (int j = 0; j < 2; j++) {
                wmma::load_matrix_sync(bh[j], bYh + ks * YLD + wn * 32 + j * 16, YLD);
                wmma::load_matrix_sync(bl[j], bYl + ks * YLD + wn * 32 + j * 16, YLD);
            }
            #pragma unroll
            for (int i = 0; i < 4; i++)
                #pragma unroll
                for (int j = 0; j < 2; j++) {
                    wmma::mma_sync(acc[i][j], ah[i], bh[j], acc[i][j]);
                    wmma::mma_sync(acc[i][j], ah[i], bl[j], acc[i][j]);
                    wmma::mma_sync(acc[i][j], al[i], bh[j], acc[i][j]);
                }
        }
        scur = (scur == 2) ? 0 : scur + 1;
        sis  = (sis  == 2) ? 0 : sis + 1;
        __syncthreads();
    }

    // ---- epilogue: stage full 128x128 fp32 tile ----
    float* cs = (float*)sm;
    #pragma unroll
    for (int i = 0; i < 4; i++)
        #pragma unroll
        for (int j = 0; j < 2; j++)
            wmma::store_matrix_sync(cs + (wm * 64 + i * 16) * CLD + wn * 32 + j * 16,
                                    acc[i][j], CLD, wmma::mem_row_major);
    __syncthreads();

    if (tileM == tileN && t < 128)
        out[((size_t)(b << 8) + tileM + t) * 8 + slot] = cs[t * CLD + t];

    if (mode < 2) {
        // bf16 hi/lo split of C
        __nv_bfloat16* ch = Chi + base;
        __nv_bfloat16* cl = Clo + base;
        #pragma unroll
        for (int it = 0; it < 8; it++) {
            int idx = t + it * 256;
            int r = idx >> 4;
            int c = (idx & 15) << 3;
            const float* sp = cs + r * CLD + c;
            float f[8];
            #pragma unroll
            for (int q = 0; q < 8; q++) f[q] = sp[q];
            uint32_t hp[4], lp[4];
            #pragma unroll
            for (int q = 0; q < 4; q++) {
                __nv_bfloat16 h0 = __float2bfloat16_rn(f[2*q]);
                __nv_bfloat16 h1 = __float2bfloat16_rn(f[2*q+1]);
                __nv_bfloat162 hh; hh.x = h0; hh.y = h1;
                hp[q] = *(uint32_t*)&hh;
                __nv_bfloat162 ll;
                ll.x = __float2bfloat16_rn(f[2*q]   - bf2f(h0));
                ll.y = __float2bfloat16_rn(f[2*q+1] - bf2f(h1));
                lp[q] = *(uint32_t*)&ll;
            }
            *(uint4*)(ch + (size_t)(tileM + r) * NN + tileN + c) = make_uint4(hp[0], hp[1], hp[2], hp[3]);
            *(uint4*)(cl + (size_t)(tileM + r) * NN + tileN + c) = make_uint4(lp[0], lp[1], lp[2], lp[3]);
        }
    }

    if (mode >= 1) {
        // partials via Slab rows x staged-C columns.
        // mode 1: pA_i += sum_j Slab[i,j] * cs[j][i]      (d5; Slab=P2)
        // mode 2: pA_i (d7) uses slabA(P3) x cs; pB_i (d6) uses slabA x slabB(P3^T block)
        const __nv_bfloat16* sh = SlabH + base;
        const __nv_bfloat16* sl = SlabL + base;
        float* spA = (float*)(sm + SPA_OFF);
        float* spB = (float*)(sm + SPB_OFF);
        int il = t >> 3, jq = t & 7;
        #pragma unroll 1
        for (int s4 = 0; s4 < 4; s4++) {
            __syncthreads();
            {   // slabA: rows i = tileN + s4*32 + (t>>3), cols tileM..+128
                int rr = t >> 3;
                int sc = (t & 7) * 16;
                size_t g = (size_t)(tileN + s4 * 32 + rr) * NN + tileM + sc;
                uint4 uh0 = *(const uint4*)(sh + g);
                uint4 uh1 = *(const uint4*)(sh + g + 8);
                uint4 ul0 = *(const uint4*)(sl + g);
                uint4 ul1 = *(const uint4*)(sl + g + 8);
                const uint32_t uh[8] = {uh0.x,uh0.y,uh0.z,uh0.w,uh1.x,uh1.y,uh1.z,uh1.w};
                const uint32_t ul[8] = {ul0.x,ul0.y,ul0.z,ul0.w,ul1.x,ul1.y,ul1.z,ul1.w};
                float* dst = spA + rr * SLDA + sc;
                #pragma unroll
                for (int q = 0; q < 8; q++) {
                    __nv_bfloat162 h = *(__nv_bfloat162*)&uh[q];
                    __nv_bfloat162 l = *(__nv_bfloat162*)&ul[q];
                    dst[2*q]   = bf2f(h.x) + bf2f(l.x);
                    dst[2*q+1] = bf2f(h.y) + bf2f(l.y);
                }
            }
            if (mode == 2) {
                // slabB: rows j = tileM + (t>>1), cols tileN + s4*32 + (t&1)*16
                int rr = t >> 1;
                int sc = (t & 1) * 16;
                size_t g = (size_t)(tileM + rr) * NN + tileN + s4 * 32 + sc;
                uint4 uh0 = *(const uint4*)(sh + g);
                uint4 uh1 = *(const uint4*)(sh + g + 8);
                uint4 ul0 = *(const uint4*)(sl + g);
                uint4 ul1 = *(const uint4*)(sl + g + 8);
                const uint32_t uh[8] = {uh0.x,uh0.y,uh0.z,uh0.w,uh1.x,uh1.y,uh1.z,uh1.w};
                const uint32_t ul[8] = {ul0.x,ul0.y,ul0.z,ul0.w,ul1.x,ul1.y,ul1.z,ul1.w};
                float* dst = spB + rr * SLDB + sc;
                #pragma unroll
                for (int q = 0; q < 8; q++) {
                    __nv_bfloat162 h = *(__nv_bfloat162*)&uh[q];
                    __nv_bfloat162 l = *(__nv_bfloat162*)&ul[q];
                    dst[2*q]   = bf2f(h.x) + bf2f(l.x);
                    dst[2*q+1] = bf2f(h.y) + bf2f(l.y);
                }
            }
            __syncthreads();

            int i_loc = s4 * 32 + il;
            float a = 0.0f, a2 = 0.0f;
            #pragma unroll
            for (int k = 0; k < 16; k++) {
                int j = jq + k * 8;
                float sa = spA[il * SLDA + j];
                a = fmaf(sa, cs[j * CLD + i_loc], a);
                if (mode == 2) a2 = fmaf(sa, spB[j * SLDB + il], a2);
            }
            a  += __shfl_down_sync(0xffffffffu, a, 4);
            a  += __shfl_down_sync(0xffffffffu, a, 2);
            a  += __shfl_down_sync(0xffffffffu, a, 1);
            if (mode == 2) {
                a2 += __shfl_down_sync(0xffffffffu, a2, 4);
                a2 += __shfl_down_sync(0xffffffffu, a2, 2);
                a2 += __shfl_down_sync(0xffffffffu, a2, 1);
            }
            if (jq == 0) {
                int gi = (tileM >> 7) * 65536 + (b << 8) + tileN + i_loc;
                pA[gi] = a;
                if (mode == 2) pB[gi] = a2;
            }
        }
    }
}

// ---------------------------------------------------------------------------
// finish: sum the two tile-partials per slot.
// ---------------------------------------------------------------------------
__global__ void __launch_bounds__(256) finish_kernel(const float* __restrict__ d5p,
                                                     const float* __restrict__ d6p,
                                                     const float* __restrict__ d7p,
                                                     float* __restrict__ out)
{
    int gi = blockIdx.x * 256 + threadIdx.x;
    size_t o = (size_t)gi * 8;
    out[o + 5] = d5p[gi] + d5p[65536 + gi];
    out[o + 6] = d6p[gi] + d6p[65536 + gi];
    out[o + 7] = d7p[gi] + d7p[65536 + gi];
}

// ---------------------------------------------------------------------------
extern "C" void kernel_launch(void* const* d_in, const int* in_sizes, int n_in,
                              void* d_out, int out_size)
{
    const float* A = (const float*)d_in[0];
    float* out = (float*)d_out;

    __nv_bfloat16 *Phi, *Plo, *P2hi, *P2lo, *P3hi, *P3lo;
    float *d5p, *d6p, *d7p;
    cudaGetSymbolAddress((void**)&Phi,  g_Phi);
    cudaGetSymbolAddress((void**)&Plo,  g_Plo);
    cudaGetSymbolAddress((void**)&P2hi, g_P2hi);
    cudaGetSymbolAddress((void**)&P2lo, g_P2lo);
    cudaGetSymbolAddress((void**)&P3hi, g_P3hi);
    cudaGetSymbolAddress((void**)&P3lo, g_P3lo);
    cudaGetSymbolAddress((void**)&d5p,  g_d5p);
    cudaGetSymbolAddress((void**)&d6p,  g_d6p);
    cudaGetSymbolAddress((void**)&d7p,  g_d7p);

    cudaFuncSetAttribute(gemm_wmma, cudaFuncAttributeMaxDynamicSharedMemorySize, GEMM_SMEM);

    // 1) P (bf16 hi/lo) + slots 0,1
    prep_kernel<<<8192, 256>>>(A, Phi, Plo, out);
    // 2) P2 = P * P + slot 2
    gemm_wmma<<<dim3(4, 256), 256, GEMM_SMEM>>>(
        0, Phi, Plo, Phi, Plo, P2hi, P2lo, 2,
        nullptr, nullptr, nullptr, nullptr, out);
    // 3) P3 = P * P2 + slot 3 + d5 partials (slab = P2)
    gemm_wmma<<<dim3(4, 256), 256, GEMM_SMEM>>>(
        1, Phi, Plo, P2hi, P2lo, P3hi, P3lo, 3,
        P2hi, P2lo, d5p, nullptr, out);
    // 4) P4 = P2 * P2 (never stored) + slot 4 + d7,d6 partials (slabs = P3)
    gemm_wmma<<<dim3(4, 256), 256, GEMM_SMEM>>>(
        2, P2hi, P2lo, P2hi, P2lo, nullptr, nullptr, 4,
        P3hi, P3lo, d7p, d6p, out);
    // 5) slots 5,6,7
    finish_kernel<<<256, 256>>>(d5p, d6p, d7p, out);
}